// round 13
// baseline (speedup 1.0000x reference)
#include <cuda_runtime.h>
#include <cuda_fp16.h>
#include <cstdint>
#include <math.h>

#define N 8192
#define E 262144
#define NW 256              // bitmap words per row
#define LISTCAP 256         // max union degree
#define GEMM_BLOCKS 128     // 64 rows per block
#define SB_BLOCKS 512       // setbits: 2 edges per thread
#define SHIFT 30.0f         // constant softmax pre-shift (overflow guard)

// ---------------- scratch (device globals; zero-initialized at module load) --
__device__ __align__(16) float          g_h[N * 64];
__device__ __align__(16) float          g_ht[N * 64];
__device__ __align__(16) __half         g_hth[N * 64];   // fp16 shadow (gathers)
__device__ __align__(16) float          g_A[N * 64];     // unnormalized aggregate
__device__ __align__(16) float          g_B[N];          // unnormalized weight sum
__device__ __align__(16) float          g_asrc[N];
__device__ __align__(16) float          g_adst[N];
__device__ __align__(16) float          g_Ssum[64];
__device__ __align__(16) float          g_part[GEMM_BLOCKS * 64];
__device__ unsigned                     g_fill[3];       // per-layer fill (ordered-int)
__device__ __align__(16) unsigned       g_selfmask[N / 32];  // self-edge bitmap (cleared in last kernel)
__device__ __align__(16) unsigned       g_bf[N * NW];    // cleared by k_build
__device__ __align__(16) unsigned       g_br[N * NW];
__device__ __align__(16) unsigned short g_nbr[N * LISTCAP];
__device__ __align__(16) int            g_cnt[N];

// ---------------- helpers ----------------
__device__ __forceinline__ float eluf(float x)  { return x > 0.f ? x : expf(x) - 1.f; }
__device__ __forceinline__ float lrelu(float x) { return x > 0.f ? x : 0.2f * x; }
__device__ __forceinline__ unsigned fmap(float f) {
    unsigned u = __float_as_uint(f);
    return (u & 0x80000000u) ? ~u : (u | 0x80000000u);
}
__device__ __forceinline__ float funmap(unsigned u) {
    return (u & 0x80000000u) ? __uint_as_float(u & 0x7fffffffu) : __uint_as_float(~u);
}
__device__ __forceinline__ unsigned h2u(__half2 h) {
    union { __half2 h; unsigned u; } c; c.h = h; return c.u;
}

// ---------------- kernels ----------------
// adjacency bits + self-edge bitmap; gid<N threads also do symbolic features.
// edge_index is int32 (JAX downcasts int64 without x64 mode).
__global__ void k_setbits_feat(const int* __restrict__ ei,
                               const float* __restrict__ x,
                               const float* __restrict__ symW,
                               const float* __restrict__ symb) {
    int gid = blockIdx.x * blockDim.x + threadIdx.x;
    if (gid == 0) { g_fill[0] = 0u; g_fill[1] = 0u; g_fill[2] = 0u; }  // no other toucher here
    int k0 = gid * 2;
    if (k0 < E) {
        int2 r2 = *(const int2*)(ei + k0);
        int2 c2 = *(const int2*)(ei + E + k0);
        if ((unsigned)r2.x < N && (unsigned)c2.x < N) {
            if (r2.x == c2.x) atomicOr(&g_selfmask[r2.x >> 5], 1u << (r2.x & 31));
            else {
                atomicOr(&g_bf[(r2.x << 8) + (c2.x >> 5)], 1u << (c2.x & 31));
                atomicOr(&g_br[(c2.x << 8) + (r2.x >> 5)], 1u << (r2.x & 31));
            }
        }
        if ((unsigned)r2.y < N && (unsigned)c2.y < N) {
            if (r2.y == c2.y) atomicOr(&g_selfmask[r2.y >> 5], 1u << (r2.y & 31));
            else {
                atomicOr(&g_bf[(r2.y << 8) + (c2.y >> 5)], 1u << (c2.y & 31));
                atomicOr(&g_br[(c2.y << 8) + (r2.y >> 5)], 1u << (r2.y & 31));
            }
        }
    }

    int i = gid;
    if (i >= N) return;
    const float* xr = x + i * 16;
    float am = xr[0], bod = xr[1], dox = xr[2], ph = xr[4], ni = xr[7];

    float p_ph  = ph  < 6.5f   ? (6.5f - ph) / 6.5f     : (ph  > 8.5f ? (ph  - 8.5f) / 8.5f : 0.f);
    float p_am  = am  < 0.001f ? (0.001f - am) / 0.001f : (am  > 0.5f ? (am  - 0.5f) / 0.5f : 0.f);
    float p_bod = bod < 0.001f ? (0.001f - bod) / 0.001f: (bod > 5.0f ? (bod - 5.0f) / 5.0f : 0.f);
    float p_do  = dox < 6.0f   ? (6.0f - dox) / 6.0f    : 0.f;
    float p_ni  = ni  < 0.001f ? (0.001f - ni) / 0.001f : (ni  > 10.f ? (ni  - 10.f) / 10.f : 0.f);

    float bact = (1.2f * am / 0.5f + 1.5f * bod / 5.0f - 0.8f * dox / 10.0f) * (1.f / 3.f);
    float chem = (1.5f * ph / 8.5f + ni / 10.0f) * 0.5f;
    float org  = (2.0f * bod / 5.0f - 1.5f * dox / 10.0f + 0.8f * am / 0.5f) * (1.f / 3.f);
    float agri = 2.0f * ni / 10.0f;
    float comp = 1.f / (1.f + (p_ph + p_am + p_bod + p_do + p_ni) + 1e-8f);

    float f[10] = { p_ph, p_am, p_bod, p_do, p_ni, bact, chem, org, agri, comp };
    float* hr = g_h + i * 64;
#pragma unroll
    for (int k = 0; k < 16; k++) hr[k] = xr[k];
    for (int j = 0; j < 32; j++) {
        float s = symb[j];
#pragma unroll
        for (int k = 0; k < 10; k++) s += f[k] * symW[j * 10 + k];
        hr[16 + j] = eluf(s);
    }
}

// one warp per row: bitmap -> canonical uint16 list; re-zero bitmap rows.
__global__ void k_build() {
    int warp = threadIdx.x >> 5;
    int lane = threadIdx.x & 31;
    int i = blockIdx.x * 8 + warp;

    unsigned* fw = g_bf + (i << 8);
    unsigned* rv = g_br + (i << 8);
    unsigned short* dst = g_nbr + i * LISTCAP;
    int total = 0;
    for (int it = 0; it < 8; it++) {
        int wi = it * 32 + lane;
        unsigned f = fw[wi];
        unsigned r = rv[wi];
        unsigned u = f | r;
        int cnt = __popc(u);
        int pre = cnt;
#pragma unroll
        for (int o = 1; o < 32; o <<= 1) {
            int t = __shfl_up_sync(0xffffffffu, pre, o);
            if (lane >= o) pre += t;
        }
        int wtot = __shfl_sync(0xffffffffu, pre, 31);
        int pos = total + pre - cnt;
        while (u) {
            int b = __ffs(u) - 1;
            u &= u - 1;
            unsigned F = (f >> b) & 1;
            unsigned R = (r >> b) & 1;
            if (pos < LISTCAP)
                dst[pos] = (unsigned short)((wi * 32 + b) | (F << 13) | (R << 14));
            pos++;
        }
        total += wtot;
        fw[wi] = 0u;
        rv[wi] = 0u;
    }
    if (total > LISTCAP) total = LISTCAP;
    if (lane == 0) g_cnt[i] = total;
}

// Fused: [mode>=1: inline combine of previous layer into g_h] ;
// ht = h @ W^T (fp32 + fp16 shadow) ; asrc/adst ; column partials.
// mode: 0 = plain load, 1 = combine (h = elu(r)), 2 = combine+residual.
__global__ void k_gemm_fused(const float* __restrict__ W,
                             const float* __restrict__ att, int K,
                             int mode, int fidx) {
    __shared__ __align__(16) float Ws[64][68];
    __shared__ float As[64][65];
    __shared__ float sAtt[128];
    __shared__ float spart[8][64];
    __shared__ float sZinv[64];
    __shared__ float sSs[64];
    __shared__ float sEnf, sEs;

    int tid = threadIdx.x;
    int rowBase = blockIdx.x * 64;

    for (int idx = tid; idx < 64 * K; idx += 256) {
        int c = idx / K, k = idx % K;
        Ws[k][c] = W[idx];
    }
    if (tid < 128) sAtt[tid] = att[tid];

    if (mode) {
        if (tid == 0) {
            float fill = funmap(g_fill[fidx]);
            sEnf = expf(-fill);
            sEs  = expf(SHIFT - fill);
        }
        if (tid < 64) sSs[tid] = g_Ssum[tid];
        __syncthreads();
        if (tid < 64) {
            float B = g_B[rowBase + tid];
            sZinv[tid] = 1.f / (1.f + 8191.f * sEnf + sEs * B);
        }
        __syncthreads();
        float enf = sEnf, es = sEs;
        for (int idx = tid; idx < 64 * K; idx += 256) {
            int r = idx / K, k = idx % K;
            int gi = (rowBase + r) * 64 + k;
            float A  = g_A[gi];
            float hi = g_ht[gi];
            float rr = (es * A + enf * sSs[k] + (1.f - enf) * hi) * sZinv[r];
            float e = eluf(rr);
            float hn = (mode == 2) ? g_h[gi] + e : e;
            g_h[gi] = hn;
            As[r][k] = hn;
        }
    } else {
        for (int idx = tid; idx < 64 * K; idx += 256) {
            int r = idx / K, k = idx % K;
            As[r][k] = g_h[(rowBase + r) * 64 + k];
        }
    }
    __syncthreads();

    int cg = tid & 7;
    int rg = tid >> 3;
    int r0 = rg * 2;
    int c0 = cg * 8;

    float acc0[8] = {}, acc1[8] = {};
    for (int k = 0; k < K; k++) {
        float a0 = As[r0][k];
        float a1 = As[r0 + 1][k];
        float4 w0 = *(const float4*)&Ws[k][c0];
        float4 w1 = *(const float4*)&Ws[k][c0 + 4];
        acc0[0] += a0 * w0.x; acc0[1] += a0 * w0.y; acc0[2] += a0 * w0.z; acc0[3] += a0 * w0.w;
        acc0[4] += a0 * w1.x; acc0[5] += a0 * w1.y; acc0[6] += a0 * w1.z; acc0[7] += a0 * w1.w;
        acc1[0] += a1 * w0.x; acc1[1] += a1 * w0.y; acc1[2] += a1 * w0.z; acc1[3] += a1 * w0.w;
        acc1[4] += a1 * w1.x; acc1[5] += a1 * w1.y; acc1[6] += a1 * w1.z; acc1[7] += a1 * w1.w;
    }

    int R0 = rowBase + r0;
    float4* hp0 = (float4*)(g_ht + R0 * 64 + c0);
    float4* hp1 = (float4*)(g_ht + (R0 + 1) * 64 + c0);
    hp0[0] = make_float4(acc0[0], acc0[1], acc0[2], acc0[3]);
    hp0[1] = make_float4(acc0[4], acc0[5], acc0[6], acc0[7]);
    hp1[0] = make_float4(acc1[0], acc1[1], acc1[2], acc1[3]);
    hp1[1] = make_float4(acc1[4], acc1[5], acc1[6], acc1[7]);

    *(uint4*)(g_hth + R0 * 64 + c0) = make_uint4(
        h2u(__floats2half2_rn(acc0[0], acc0[1])),
        h2u(__floats2half2_rn(acc0[2], acc0[3])),
        h2u(__floats2half2_rn(acc0[4], acc0[5])),
        h2u(__floats2half2_rn(acc0[6], acc0[7])));
    *(uint4*)(g_hth + (R0 + 1) * 64 + c0) = make_uint4(
        h2u(__floats2half2_rn(acc1[0], acc1[1])),
        h2u(__floats2half2_rn(acc1[2], acc1[3])),
        h2u(__floats2half2_rn(acc1[4], acc1[5])),
        h2u(__floats2half2_rn(acc1[6], acc1[7])));

    float s0 = 0.f, d0 = 0.f, s1 = 0.f, d1 = 0.f;
#pragma unroll
    for (int m = 0; m < 8; m++) {
        float aw = sAtt[c0 + m], dw = sAtt[64 + c0 + m];
        s0 += acc0[m] * aw;  d0 += acc0[m] * dw;
        s1 += acc1[m] * aw;  d1 += acc1[m] * dw;
    }
#pragma unroll
    for (int o = 1; o < 8; o <<= 1) {
        s0 += __shfl_xor_sync(0xffffffffu, s0, o);
        d0 += __shfl_xor_sync(0xffffffffu, d0, o);
        s1 += __shfl_xor_sync(0xffffffffu, s1, o);
        d1 += __shfl_xor_sync(0xffffffffu, d1, o);
    }
    if (cg == 0) {
        g_asrc[R0] = s0;  g_adst[R0] = d0;
        g_asrc[R0 + 1] = s1;  g_adst[R0 + 1] = d1;
    }

    int lane = tid & 31, warp = tid >> 5;
    float colv[8];
#pragma unroll
    for (int m = 0; m < 8; m++) {
        float v = acc0[m] + acc1[m];
        v += __shfl_xor_sync(0xffffffffu, v, 8);
        v += __shfl_xor_sync(0xffffffffu, v, 16);
        colv[m] = v;
    }
    if (lane < 8) {
#pragma unroll
        for (int m = 0; m < 8; m++) spart[warp][lane * 8 + m] = colv[m];
    }
    __syncthreads();
    if (tid < 64) {
        float s = 0.f;
#pragma unroll
        for (int w = 0; w < 8; w++) s += spart[w][tid];
        g_part[blockIdx.x * 64 + tid] = s;
    }
}

// one warp per row: unnormalized sparse aggregate A_i/B_i (shift S), plus
// fill-max (forward entries + self edges) and Ssum reduction (block 0).
__global__ void k_agg2(int fidx) {
    __shared__ unsigned short list[8][LISTCAP];
    __shared__ float wbuf[8][LISTCAP];
    __shared__ float red[256];
    int tid = threadIdx.x;
    int warp = tid >> 5;
    int lane = tid & 31;
    int i = blockIdx.x * 8 + warp;

    if (blockIdx.x == 0) {
        int col = tid & 63, q = tid >> 6;
        float s = 0.f;
        for (int b = q; b < GEMM_BLOCKS; b += 4) s += g_part[b * 64 + col];
        red[tid] = s;
        __syncthreads();
        if (tid < 64) g_Ssum[tid] = red[tid] + red[64 + tid] + red[128 + tid] + red[192 + tid];
        // self-edge fill contributions (diag entries of e)
        unsigned mw = g_selfmask[tid];
        float sm = -3.0e38f;
        while (mw) {
            int b = __ffs(mw) - 1; mw &= mw - 1;
            int si = tid * 32 + b;
            sm = fmaxf(sm, lrelu(g_asrc[si] + g_adst[si]));
        }
        if (sm > -3.0e38f) atomicMax(&g_fill[fidx], fmap(sm));
    }

    int total = g_cnt[i];
    const unsigned* src = (const unsigned*)(g_nbr + i * LISTCAP);
    unsigned* dstw = (unsigned*)&list[warp][0];
    for (int t = lane; t * 2 < total; t += 32) dstw[t] = src[t];
    __syncwarp();

    const float ENS = expf(-SHIFT);
    float ai = g_asrc[i];
    float di = g_adst[i];
    float z = 0.f;
    float mv = -3.0e38f;
    for (int n = lane; n < total; n += 32) {
        unsigned ent = list[warp][n];
        int j = ent & 8191;
        float aj = g_asrc[j];
        float dj = g_adst[j];
        float e1 = 0.f, e2 = 0.f;
        if (ent & (1u << 13)) { e1 = lrelu(ai + dj); mv = fmaxf(mv, e1); }
        if (ent & (1u << 14)) { e2 = lrelu(aj + di); }
        float w = expf(0.5f * (e1 + e2) - SHIFT) - ENS;
        wbuf[warp][n] = w;
        z += w;
    }
#pragma unroll
    for (int o = 16; o; o >>= 1) {
        z  += __shfl_xor_sync(0xffffffffu, z, o);
        mv  = fmaxf(mv, __shfl_xor_sync(0xffffffffu, mv, o));
    }
    if (lane == 0) {
        g_B[i] = z;
        if (mv > -3.0e38f) atomicMax(&g_fill[fidx], fmap(mv));
    }
    __syncwarp();

    int c0 = lane * 2;
    float acc0 = 0.f, acc1 = 0.f;
    int n = 0;
    for (; n + 3 < total; n += 4) {
        float w0 = wbuf[warp][n],     w1 = wbuf[warp][n + 1];
        float w2 = wbuf[warp][n + 2], w3 = wbuf[warp][n + 3];
        int j0 = list[warp][n] & 8191,     j1 = list[warp][n + 1] & 8191;
        int j2 = list[warp][n + 2] & 8191, j3 = list[warp][n + 3] & 8191;
        float2 h0 = __half22float2(*(const __half2*)(g_hth + j0 * 64 + c0));
        float2 h1 = __half22float2(*(const __half2*)(g_hth + j1 * 64 + c0));
        float2 h2 = __half22float2(*(const __half2*)(g_hth + j2 * 64 + c0));
        float2 h3 = __half22float2(*(const __half2*)(g_hth + j3 * 64 + c0));
        acc0 += w0 * h0.x + w1 * h1.x + w2 * h2.x + w3 * h3.x;
        acc1 += w0 * h0.y + w1 * h1.y + w2 * h2.y + w3 * h3.y;
    }
    for (; n < total; n++) {
        float w0 = wbuf[warp][n];
        int j0 = list[warp][n] & 8191;
        float2 h0 = __half22float2(*(const __half2*)(g_hth + j0 * 64 + c0));
        acc0 += w0 * h0.x;
        acc1 += w0 * h0.y;
    }
    g_A[i * 64 + c0]     = acc0;
    g_A[i * 64 + c0 + 1] = acc1;
}

// final: combine layer-2 aggregate + residual + both head MLPs + outputs.
// Also clears g_selfmask for the next replay (no reader of it here).
__global__ void k_combine_heads(const float* __restrict__ rW1, const float* __restrict__ rb1,
                                const float* __restrict__ rW2, const float* __restrict__ rb2,
                                const float* __restrict__ cW1, const float* __restrict__ cb1,
                                const float* __restrict__ cW2, const float* __restrict__ cb2,
                                float* __restrict__ out) {
    __shared__ float sRW1[32][65];
    __shared__ float sCW1[32][65];
    __shared__ float sRW2[32];
    __shared__ float sCW2[128];
    __shared__ float sRb1[32];
    __shared__ float sCb1[32];
    __shared__ float srow[8][64];
    __shared__ float sEnf, sEs;

    int tid = threadIdx.x;
    int warp = tid >> 5;
    int lane = tid & 31;
    int i = blockIdx.x * 8 + warp;
    int c0 = lane * 2;

    if (blockIdx.x == 0) g_selfmask[tid] = 0u;   // blockDim==256==N/32; no reader here

    for (int idx = tid; idx < 2048; idx += 256) {
        sRW1[idx >> 6][idx & 63] = rW1[idx];
        sCW1[idx >> 6][idx & 63] = cW1[idx];
    }
    if (tid < 32) { sRW2[tid] = rW2[tid]; sRb1[tid] = rb1[tid]; sCb1[tid] = cb1[tid]; }
    if (tid < 128) sCW2[tid] = cW2[tid];
    if (tid == 0) {
        float fill = funmap(g_fill[2]);
        sEnf = expf(-fill);
        sEs  = expf(SHIFT - fill);
    }
    __syncthreads();

    float enf = sEnf, es = sEs;
    float Zinv;
    if (lane == 0) Zinv = 1.f / (1.f + 8191.f * enf + es * g_B[i]);
    Zinv = __shfl_sync(0xffffffffu, Zinv, 0);

    float A0 = g_A[i * 64 + c0], A1 = g_A[i * 64 + c0 + 1];
    float hi0 = g_ht[i * 64 + c0], hi1 = g_ht[i * 64 + c0 + 1];
    float r0 = (es * A0 + enf * g_Ssum[c0]     + (1.f - enf) * hi0) * Zinv;
    float r1 = (es * A1 + enf * g_Ssum[c0 + 1] + (1.f - enf) * hi1) * Zinv;
    float h0 = g_h[i * 64 + c0]     + eluf(r0);
    float h1 = g_h[i * 64 + c0 + 1] + eluf(r1);

    srow[warp][c0]     = h0;
    srow[warp][c0 + 1] = h1;
    __syncwarp();

    float t1 = sRb1[lane];
    float t2 = sCb1[lane];
#pragma unroll
    for (int k = 0; k < 64; k++) {
        float hv = srow[warp][k];
        t1 += hv * sRW1[lane][k];
        t2 += hv * sCW1[lane][k];
    }
    t1 = eluf(t1);
    t2 = eluf(t2);

    float p = t1 * sRW2[lane];
#pragma unroll
    for (int o = 16; o; o >>= 1) p += __shfl_xor_sync(0xffffffffu, p, o);
    if (lane == 0) out[i] = p + rb2[0];

#pragma unroll
    for (int k = 0; k < 4; k++) {
        float q = t2 * sCW2[k * 32 + lane];
#pragma unroll
        for (int o = 16; o; o >>= 1) q += __shfl_xor_sync(0xffffffffu, q, o);
        if (lane == 0) out[N + i * 4 + k] = q + cb2[k];
    }

    ((float2*)(out + N + 4 * N))[i * 32 + lane] = make_float2(h0, h1);
}

// ---------------- launch ----------------
extern "C" void kernel_launch(void* const* d_in, const int* in_sizes, int n_in,
                              void* d_out, int out_size) {
    const float* x    = (const float*)d_in[0];
    const int*   ei   = (const int*)d_in[1];   // int32 (JAX downcast)
    const float* symW = (const float*)d_in[3];
    const float* symb = (const float*)d_in[4];
    const float* W0   = (const float*)d_in[5];
    const float* att0 = (const float*)d_in[6];
    const float* W1   = (const float*)d_in[7];
    const float* att1 = (const float*)d_in[8];
    const float* W2   = (const float*)d_in[9];
    const float* att2 = (const float*)d_in[10];
    const float* rW1  = (const float*)d_in[11];
    const float* rb1  = (const float*)d_in[12];
    const float* rW2  = (const float*)d_in[13];
    const float* rb2  = (const float*)d_in[14];
    const float* cW1  = (const float*)d_in[15];
    const float* cb1  = (const float*)d_in[16];
    const float* cW2  = (const float*)d_in[17];
    const float* cb2  = (const float*)d_in[18];
    float* out = (float*)d_out;

    k_setbits_feat<<<SB_BLOCKS, 256>>>(ei, x, symW, symb);
    k_build<<<1024, 256>>>();

    k_gemm_fused<<<GEMM_BLOCKS, 256>>>(W0, att0, 48, 0, 0);
    k_agg2<<<1024, 256>>>(0);
    k_gemm_fused<<<GEMM_BLOCKS, 256>>>(W1, att1, 64, 1, 0);   // inline combine L0
    k_agg2<<<1024, 256>>>(1);
    k_gemm_fused<<<GEMM_BLOCKS, 256>>>(W2, att2, 64, 2, 1);   // inline combine L1 (+resid)
    k_agg2<<<1024, 256>>>(2);
    k_combine_heads<<<1024, 256>>>(rW1, rb1, rW2, rb2, cW1, cb1, cW2, cb2, out);
}

// round 16
// speedup vs baseline: 1.0473x; 1.0473x over previous
#include <cuda_runtime.h>
#include <cuda_fp16.h>
#include <cstdint>
#include <math.h>

#define N 8192
#define E 262144
#define NW 256              // bitmap words per row
#define LISTCAP 256         // max union degree
#define GEMM_BLOCKS 128     // 64 rows per block
#define SB_BLOCKS 512       // setbits: 2 edges per thread
#define SHIFT 30.0f         // constant softmax pre-shift (overflow guard)

// ---------------- scratch (device globals; zero-initialized at module load) --
__device__ __align__(16) float          g_h[N * 64];
__device__ __align__(16) float          g_ht[N * 64];
__device__ __align__(16) __half         g_hth[N * 64];   // fp16 shadow (gathers)
__device__ __align__(16) float          g_A[N * 64];     // unnormalized aggregate
__device__ __align__(16) float          g_B[N];          // unnormalized weight sum
__device__ __align__(16) float          g_asrc[N];
__device__ __align__(16) float          g_adst[N];
__device__ __align__(16) float          g_Ssum[64];
__device__ __align__(16) float          g_part[GEMM_BLOCKS * 64];
__device__ unsigned                     g_fill[3];       // per-layer fill (ordered-int)
__device__ __align__(16) unsigned       g_selfmask[N / 32];  // cleared in last kernel
__device__ __align__(16) unsigned       g_bf[N * NW];    // cleared by k_build
__device__ __align__(16) unsigned       g_br[N * NW];
__device__ __align__(16) unsigned short g_nbr[N * LISTCAP];
__device__ __align__(16) int            g_cnt[N];

// ---------------- helpers ----------------
__device__ __forceinline__ float eluf(float x)  { return x > 0.f ? x : expf(x) - 1.f; }
__device__ __forceinline__ float lrelu(float x) { return x > 0.f ? x : 0.2f * x; }
__device__ __forceinline__ unsigned fmap(float f) {
    unsigned u = __float_as_uint(f);
    return (u & 0x80000000u) ? ~u : (u | 0x80000000u);
}
__device__ __forceinline__ float funmap(unsigned u) {
    return (u & 0x80000000u) ? __uint_as_float(u & 0x7fffffffu) : __uint_as_float(~u);
}
__device__ __forceinline__ unsigned h2u(__half2 h) {
    union { __half2 h; unsigned u; } c; c.h = h; return c.u;
}

// ---------------- kernels ----------------
// adjacency bits + self-edge bitmap; gid<N threads also do symbolic features.
// edge_index is int32 (JAX downcasts int64 without x64 mode).
__global__ void k_setbits_feat(const int* __restrict__ ei,
                               const float* __restrict__ x,
                               const float* __restrict__ symW,
                               const float* __restrict__ symb) {
    int gid = blockIdx.x * blockDim.x + threadIdx.x;
    if (gid == 0) { g_fill[0] = 0u; g_fill[1] = 0u; g_fill[2] = 0u; }
    int k0 = gid * 2;
    if (k0 < E) {
        int2 r2 = *(const int2*)(ei + k0);
        int2 c2 = *(const int2*)(ei + E + k0);
        if ((unsigned)r2.x < N && (unsigned)c2.x < N) {
            if (r2.x == c2.x) atomicOr(&g_selfmask[r2.x >> 5], 1u << (r2.x & 31));
            else {
                atomicOr(&g_bf[(r2.x << 8) + (c2.x >> 5)], 1u << (c2.x & 31));
                atomicOr(&g_br[(c2.x << 8) + (r2.x >> 5)], 1u << (r2.x & 31));
            }
        }
        if ((unsigned)r2.y < N && (unsigned)c2.y < N) {
            if (r2.y == c2.y) atomicOr(&g_selfmask[r2.y >> 5], 1u << (r2.y & 31));
            else {
                atomicOr(&g_bf[(r2.y << 8) + (c2.y >> 5)], 1u << (c2.y & 31));
                atomicOr(&g_br[(c2.y << 8) + (r2.y >> 5)], 1u << (r2.y & 31));
            }
        }
    }

    int i = gid;
    if (i >= N) return;
    const float* xr = x + i * 16;
    float am = xr[0], bod = xr[1], dox = xr[2], ph = xr[4], ni = xr[7];

    float p_ph  = ph  < 6.5f   ? (6.5f - ph) / 6.5f     : (ph  > 8.5f ? (ph  - 8.5f) / 8.5f : 0.f);
    float p_am  = am  < 0.001f ? (0.001f - am) / 0.001f : (am  > 0.5f ? (am  - 0.5f) / 0.5f : 0.f);
    float p_bod = bod < 0.001f ? (0.001f - bod) / 0.001f: (bod > 5.0f ? (bod - 5.0f) / 5.0f : 0.f);
    float p_do  = dox < 6.0f   ? (6.0f - dox) / 6.0f    : 0.f;
    float p_ni  = ni  < 0.001f ? (0.001f - ni) / 0.001f : (ni  > 10.f ? (ni  - 10.f) / 10.f : 0.f);

    float bact = (1.2f * am / 0.5f + 1.5f * bod / 5.0f - 0.8f * dox / 10.0f) * (1.f / 3.f);
    float chem = (1.5f * ph / 8.5f + ni / 10.0f) * 0.5f;
    float org  = (2.0f * bod / 5.0f - 1.5f * dox / 10.0f + 0.8f * am / 0.5f) * (1.f / 3.f);
    float agri = 2.0f * ni / 10.0f;
    float comp = 1.f / (1.f + (p_ph + p_am + p_bod + p_do + p_ni) + 1e-8f);

    float f[10] = { p_ph, p_am, p_bod, p_do, p_ni, bact, chem, org, agri, comp };
    float* hr = g_h + i * 64;
#pragma unroll
    for (int k = 0; k < 16; k++) hr[k] = xr[k];
    for (int j = 0; j < 32; j++) {
        float s = symb[j];
#pragma unroll
        for (int k = 0; k < 10; k++) s += f[k] * symW[j * 10 + k];
        hr[16 + j] = eluf(s);
    }
}

// one warp per row: bitmap -> canonical uint16 list; re-zero bitmap rows.
__global__ void k_build() {
    int warp = threadIdx.x >> 5;
    int lane = threadIdx.x & 31;
    int i = blockIdx.x * 8 + warp;

    unsigned* fw = g_bf + (i << 8);
    unsigned* rv = g_br + (i << 8);
    unsigned short* dst = g_nbr + i * LISTCAP;
    int total = 0;
    for (int it = 0; it < 8; it++) {
        int wi = it * 32 + lane;
        unsigned f = fw[wi];
        unsigned r = rv[wi];
        unsigned u = f | r;
        int cnt = __popc(u);
        int pre = cnt;
#pragma unroll
        for (int o = 1; o < 32; o <<= 1) {
            int t = __shfl_up_sync(0xffffffffu, pre, o);
            if (lane >= o) pre += t;
        }
        int wtot = __shfl_sync(0xffffffffu, pre, 31);
        int pos = total + pre - cnt;
        while (u) {
            int b = __ffs(u) - 1;
            u &= u - 1;
            unsigned F = (f >> b) & 1;
            unsigned R = (r >> b) & 1;
            if (pos < LISTCAP)
                dst[pos] = (unsigned short)((wi * 32 + b) | (F << 13) | (R << 14));
            pos++;
        }
        total += wtot;
        fw[wi] = 0u;
        rv[wi] = 0u;
    }
    if (total > LISTCAP) total = LISTCAP;
    if (lane == 0) g_cnt[i] = total;
}

// Fused: [mode>=1: inline combine of previous layer into g_h] ;
// ht = h @ W^T (fp32 + fp16 shadow) ; asrc/adst ; column partials.
// mode: 0 = plain load, 1 = combine (h = elu(r)), 2 = combine+residual.
__global__ void k_gemm_fused(const float* __restrict__ W,
                             const float* __restrict__ att, int K,
                             int mode, int fidx) {
    __shared__ __align__(16) float Ws[64][68];
    __shared__ float As[64][65];
    __shared__ float sAtt[128];
    __shared__ float spart[8][64];
    __shared__ float sZinv[64];
    __shared__ float sSs[64];
    __shared__ float sEnf, sEs;

    int tid = threadIdx.x;
    int rowBase = blockIdx.x * 64;

    for (int idx = tid; idx < 64 * K; idx += 256) {
        int c = idx / K, k = idx % K;
        Ws[k][c] = W[idx];
    }
    if (tid < 128) sAtt[tid] = att[tid];

    if (mode) {
        if (tid == 0) {
            float fill = funmap(g_fill[fidx]);
            sEnf = expf(-fill);
            sEs  = expf(SHIFT - fill);
        }
        if (tid < 64) sSs[tid] = g_Ssum[tid];
        __syncthreads();
        if (tid < 64) {
            float B = g_B[rowBase + tid];
            sZinv[tid] = 1.f / (1.f + 8191.f * sEnf + sEs * B);
        }
        __syncthreads();
        float enf = sEnf, es = sEs;
        for (int idx = tid; idx < 64 * K; idx += 256) {
            int r = idx / K, k = idx % K;
            int gi = (rowBase + r) * 64 + k;
            float A  = g_A[gi];
            float hi = g_ht[gi];
            float rr = (es * A + enf * sSs[k] + (1.f - enf) * hi) * sZinv[r];
            float e = eluf(rr);
            float hn = (mode == 2) ? g_h[gi] + e : e;
            g_h[gi] = hn;
            As[r][k] = hn;
        }
    } else {
        for (int idx = tid; idx < 64 * K; idx += 256) {
            int r = idx / K, k = idx % K;
            As[r][k] = g_h[(rowBase + r) * 64 + k];
        }
    }
    __syncthreads();

    int cg = tid & 7;
    int rg = tid >> 3;
    int r0 = rg * 2;
    int c0 = cg * 8;

    float acc0[8] = {}, acc1[8] = {};
    for (int k = 0; k < K; k++) {
        float a0 = As[r0][k];
        float a1 = As[r0 + 1][k];
        float4 w0 = *(const float4*)&Ws[k][c0];
        float4 w1 = *(const float4*)&Ws[k][c0 + 4];
        acc0[0] += a0 * w0.x; acc0[1] += a0 * w0.y; acc0[2] += a0 * w0.z; acc0[3] += a0 * w0.w;
        acc0[4] += a0 * w1.x; acc0[5] += a0 * w1.y; acc0[6] += a0 * w1.z; acc0[7] += a0 * w1.w;
        acc1[0] += a1 * w0.x; acc1[1] += a1 * w0.y; acc1[2] += a1 * w0.z; acc1[3] += a1 * w0.w;
        acc1[4] += a1 * w1.x; acc1[5] += a1 * w1.y; acc1[6] += a1 * w1.z; acc1[7] += a1 * w1.w;
    }

    int R0 = rowBase + r0;
    float4* hp0 = (float4*)(g_ht + R0 * 64 + c0);
    float4* hp1 = (float4*)(g_ht + (R0 + 1) * 64 + c0);
    hp0[0] = make_float4(acc0[0], acc0[1], acc0[2], acc0[3]);
    hp0[1] = make_float4(acc0[4], acc0[5], acc0[6], acc0[7]);
    hp1[0] = make_float4(acc1[0], acc1[1], acc1[2], acc1[3]);
    hp1[1] = make_float4(acc1[4], acc1[5], acc1[6], acc1[7]);

    *(uint4*)(g_hth + R0 * 64 + c0) = make_uint4(
        h2u(__floats2half2_rn(acc0[0], acc0[1])),
        h2u(__floats2half2_rn(acc0[2], acc0[3])),
        h2u(__floats2half2_rn(acc0[4], acc0[5])),
        h2u(__floats2half2_rn(acc0[6], acc0[7])));
    *(uint4*)(g_hth + (R0 + 1) * 64 + c0) = make_uint4(
        h2u(__floats2half2_rn(acc1[0], acc1[1])),
        h2u(__floats2half2_rn(acc1[2], acc1[3])),
        h2u(__floats2half2_rn(acc1[4], acc1[5])),
        h2u(__floats2half2_rn(acc1[6], acc1[7])));

    float s0 = 0.f, d0 = 0.f, s1 = 0.f, d1 = 0.f;
#pragma unroll
    for (int m = 0; m < 8; m++) {
        float aw = sAtt[c0 + m], dw = sAtt[64 + c0 + m];
        s0 += acc0[m] * aw;  d0 += acc0[m] * dw;
        s1 += acc1[m] * aw;  d1 += acc1[m] * dw;
    }
#pragma unroll
    for (int o = 1; o < 8; o <<= 1) {
        s0 += __shfl_xor_sync(0xffffffffu, s0, o);
        d0 += __shfl_xor_sync(0xffffffffu, d0, o);
        s1 += __shfl_xor_sync(0xffffffffu, s1, o);
        d1 += __shfl_xor_sync(0xffffffffu, d1, o);
    }
    if (cg == 0) {
        g_asrc[R0] = s0;  g_adst[R0] = d0;
        g_asrc[R0 + 1] = s1;  g_adst[R0 + 1] = d1;
    }

    int lane = tid & 31, warp = tid >> 5;
    float colv[8];
#pragma unroll
    for (int m = 0; m < 8; m++) {
        float v = acc0[m] + acc1[m];
        v += __shfl_xor_sync(0xffffffffu, v, 8);
        v += __shfl_xor_sync(0xffffffffu, v, 16);
        colv[m] = v;
    }
    if (lane < 8) {
#pragma unroll
        for (int m = 0; m < 8; m++) spart[warp][lane * 8 + m] = colv[m];
    }
    __syncthreads();
    if (tid < 64) {
        float s = 0.f;
#pragma unroll
        for (int w = 0; w < 8; w++) s += spart[w][tid];
        g_part[blockIdx.x * 64 + tid] = s;
    }
}

// one warp per row: unnormalized sparse aggregate A_i/B_i (shift S).
// Phase A uses selects; fill-max is block-reduced to ONE atomic per block.
// Phase B identical to the measured R13/R12 form. Ssum + self-fill in block 0.
__global__ void k_agg2(int fidx) {
    __shared__ unsigned short list[8][LISTCAP];
    __shared__ float wbuf[8][LISTCAP];
    __shared__ float red[256];
    __shared__ float wfill[8];
    int tid = threadIdx.x;
    int warp = tid >> 5;
    int lane = tid & 31;
    int i = blockIdx.x * 8 + warp;

    if (blockIdx.x == 0) {
        int col = tid & 63, q = tid >> 6;
        float s = 0.f;
        for (int b = q; b < GEMM_BLOCKS; b += 4) s += g_part[b * 64 + col];
        red[tid] = s;
        __syncthreads();
        if (tid < 64) g_Ssum[tid] = red[tid] + red[64 + tid] + red[128 + tid] + red[192 + tid];
        // self-edge fill contributions (diag entries of e)
        unsigned mw = g_selfmask[tid];
        float sm = -3.0e38f;
        while (mw) {
            int b = __ffs(mw) - 1; mw &= mw - 1;
            int si = tid * 32 + b;
            sm = fmaxf(sm, lrelu(g_asrc[si] + g_adst[si]));
        }
        if (sm > -3.0e38f) atomicMax(&g_fill[fidx], fmap(sm));
    }

    int total = g_cnt[i];
    const unsigned* src = (const unsigned*)(g_nbr + i * LISTCAP);
    unsigned* dstw = (unsigned*)&list[warp][0];
    for (int t = lane; t * 2 < total; t += 32) dstw[t] = src[t];
    __syncwarp();

    // phase A: weights via selects; forward-edge max for fill
    const float ENS = expf(-SHIFT);
    float ai = g_asrc[i];
    float di = g_adst[i];
    float z = 0.f;
    float mv = -3.0e38f;
    for (int n = lane; n < total; n += 32) {
        unsigned ent = list[warp][n];
        int j = ent & 8191;
        float aj = g_asrc[j];
        float dj = g_adst[j];
        float e1 = (ent & (1u << 13)) ? lrelu(ai + dj) : 0.f;
        float e2 = (ent & (1u << 14)) ? lrelu(aj + di) : 0.f;
        mv = fmaxf(mv, (ent & (1u << 13)) ? e1 : -3.0e38f);
        float w = expf(0.5f * (e1 + e2) - SHIFT) - ENS;
        wbuf[warp][n] = w;
        z += w;
    }
#pragma unroll
    for (int o = 16; o; o >>= 1) {
        z  += __shfl_xor_sync(0xffffffffu, z, o);
        mv  = fmaxf(mv, __shfl_xor_sync(0xffffffffu, mv, o));
    }
    if (lane == 0) { g_B[i] = z; wfill[warp] = mv; }
    __syncthreads();
    if (tid == 0) {
        float bm = wfill[0];
#pragma unroll
        for (int w = 1; w < 8; w++) bm = fmaxf(bm, wfill[w]);
        if (bm > -3.0e38f) atomicMax(&g_fill[fidx], fmap(bm));
    }

    // phase B: weighted accumulation (measured R13 form), unroll 4
    int c0 = lane * 2;
    float acc0 = 0.f, acc1 = 0.f;
    int n = 0;
    for (; n + 3 < total; n += 4) {
        float w0 = wbuf[warp][n],     w1 = wbuf[warp][n + 1];
        float w2 = wbuf[warp][n + 2], w3 = wbuf[warp][n + 3];
        int j0 = list[warp][n] & 8191,     j1 = list[warp][n + 1] & 8191;
        int j2 = list[warp][n + 2] & 8191, j3 = list[warp][n + 3] & 8191;
        float2 h0 = __half22float2(*(const __half2*)(g_hth + j0 * 64 + c0));
        float2 h1 = __half22float2(*(const __half2*)(g_hth + j1 * 64 + c0));
        float2 h2 = __half22float2(*(const __half2*)(g_hth + j2 * 64 + c0));
        float2 h3 = __half22float2(*(const __half2*)(g_hth + j3 * 64 + c0));
        acc0 += w0 * h0.x + w1 * h1.x + w2 * h2.x + w3 * h3.x;
        acc1 += w0 * h0.y + w1 * h1.y + w2 * h2.y + w3 * h3.y;
    }
    for (; n < total; n++) {
        float w0 = wbuf[warp][n];
        int j0 = list[warp][n] & 8191;
        float2 h0 = __half22float2(*(const __half2*)(g_hth + j0 * 64 + c0));
        acc0 += w0 * h0.x;
        acc1 += w0 * h0.y;
    }
    g_A[i * 64 + c0]     = acc0;
    g_A[i * 64 + c0 + 1] = acc1;
}

// final: combine layer-2 aggregate + residual + both head MLPs + outputs.
// Also clears g_selfmask for the next replay (no reader of it here).
__global__ void k_combine_heads(const float* __restrict__ rW1, const float* __restrict__ rb1,
                                const float* __restrict__ rW2, const float* __restrict__ rb2,
                                const float* __restrict__ cW1, const float* __restrict__ cb1,
                                const float* __restrict__ cW2, const float* __restrict__ cb2,
                                float* __restrict__ out) {
    __shared__ float sRW1[32][65];
    __shared__ float sCW1[32][65];
    __shared__ float sRW2[32];
    __shared__ float sCW2[128];
    __shared__ float sRb1[32];
    __shared__ float sCb1[32];
    __shared__ float srow[8][64];
    __shared__ float sEnf, sEs;

    int tid = threadIdx.x;
    int warp = tid >> 5;
    int lane = tid & 31;
    int i = blockIdx.x * 8 + warp;
    int c0 = lane * 2;

    if (blockIdx.x == 0) g_selfmask[tid] = 0u;   // blockDim==256==N/32

    for (int idx = tid; idx < 2048; idx += 256) {
        sRW1[idx >> 6][idx & 63] = rW1[idx];
        sCW1[idx >> 6][idx & 63] = cW1[idx];
    }
    if (tid < 32) { sRW2[tid] = rW2[tid]; sRb1[tid] = rb1[tid]; sCb1[tid] = cb1[tid]; }
    if (tid < 128) sCW2[tid] = cW2[tid];
    if (tid == 0) {
        float fill = funmap(g_fill[2]);
        sEnf = expf(-fill);
        sEs  = expf(SHIFT - fill);
    }
    __syncthreads();

    float enf = sEnf, es = sEs;
    float Zinv;
    if (lane == 0) Zinv = 1.f / (1.f + 8191.f * enf + es * g_B[i]);
    Zinv = __shfl_sync(0xffffffffu, Zinv, 0);

    float A0 = g_A[i * 64 + c0], A1 = g_A[i * 64 + c0 + 1];
    float hi0 = g_ht[i * 64 + c0], hi1 = g_ht[i * 64 + c0 + 1];
    float r0 = (es * A0 + enf * g_Ssum[c0]     + (1.f - enf) * hi0) * Zinv;
    float r1 = (es * A1 + enf * g_Ssum[c0 + 1] + (1.f - enf) * hi1) * Zinv;
    float h0 = g_h[i * 64 + c0]     + eluf(r0);
    float h1 = g_h[i * 64 + c0 + 1] + eluf(r1);

    srow[warp][c0]     = h0;
    srow[warp][c0 + 1] = h1;
    __syncwarp();

    float t1 = sRb1[lane];
    float t2 = sCb1[lane];
#pragma unroll
    for (int k = 0; k < 64; k++) {
        float hv = srow[warp][k];
        t1 += hv * sRW1[lane][k];
        t2 += hv * sCW1[lane][k];
    }
    t1 = eluf(t1);
    t2 = eluf(t2);

    float p = t1 * sRW2[lane];
#pragma unroll
    for (int o = 16; o; o >>= 1) p += __shfl_xor_sync(0xffffffffu, p, o);
    if (lane == 0) out[i] = p + rb2[0];

#pragma unroll
    for (int k = 0; k < 4; k++) {
        float q = t2 * sCW2[k * 32 + lane];
#pragma unroll
        for (int o = 16; o; o >>= 1) q += __shfl_xor_sync(0xffffffffu, q, o);
        if (lane == 0) out[N + i * 4 + k] = q + cb2[k];
    }

    ((float2*)(out + N + 4 * N))[i * 32 + lane] = make_float2(h0, h1);
}

// ---------------- launch ----------------
extern "C" void kernel_launch(void* const* d_in, const int* in_sizes, int n_in,
                              void* d_out, int out_size) {
    const float* x    = (const float*)d_in[0];
    const int*   ei   = (const int*)d_in[1];   // int32 (JAX downcast)
    const float* symW = (const float*)d_in[3];
    const float* symb = (const float*)d_in[4];
    const float* W0   = (const float*)d_in[5];
    const float* att0 = (const float*)d_in[6];
    const float* W1   = (const float*)d_in[7];
    const float* att1 = (const float*)d_in[8];
    const float* W2   = (const float*)d_in[9];
    const float* att2 = (const float*)d_in[10];
    const float* rW1  = (const float*)d_in[11];
    const float* rb1  = (const float*)d_in[12];
    const float* rW2  = (const float*)d_in[13];
    const float* rb2  = (const float*)d_in[14];
    const float* cW1  = (const float*)d_in[15];
    const float* cb1  = (const float*)d_in[16];
    const float* cW2  = (const float*)d_in[17];
    const float* cb2  = (const float*)d_in[18];
    float* out = (float*)d_out;

    k_setbits_feat<<<SB_BLOCKS, 256>>>(ei, x, symW, symb);
    k_build<<<1024, 256>>>();

    k_gemm_fused<<<GEMM_BLOCKS, 256>>>(W0, att0, 48, 0, 0);
    k_agg2<<<1024, 256>>>(0);
    k_gemm_fused<<<GEMM_BLOCKS, 256>>>(W1, att1, 64, 1, 0);   // inline combine L0
    k_agg2<<<1024, 256>>>(1);
    k_gemm_fused<<<GEMM_BLOCKS, 256>>>(W2, att2, 64, 2, 1);   // inline combine L1 (+resid)
    k_agg2<<<1024, 256>>>(2);
    k_combine_heads<<<1024, 256>>>(rW1, rb1, rW2, rb2, cW1, cb1, cW2, cb2, out);
}

// round 17
// speedup vs baseline: 1.1201x; 1.0695x over previous
#include <cuda_runtime.h>
#include <cuda_fp16.h>
#include <cstdint>
#include <math.h>

#define N 8192
#define E 262144
#define NW 256              // bitmap words per row
#define LISTCAP 256         // max union degree
#define LISTPAD 260         // LISTCAP + pad slots (odd-total zero entry)
#define GEMM_BLOCKS 128     // 64 rows per block
#define SB_BLOCKS 512       // setbits: 2 edges per thread
#define SHIFT 30.0f         // constant softmax pre-shift (overflow guard)

// ---------------- scratch (device globals; zero-initialized at module load) --
__device__ __align__(16) float          g_h[N * 64];
__device__ __align__(16) float          g_ht[N * 64];
__device__ __align__(16) __half         g_hth[N * 64];   // fp16 shadow (gathers)
__device__ __align__(16) float          g_A[N * 64];     // unnormalized aggregate
__device__ __align__(16) float          g_B[N];          // unnormalized weight sum
__device__ __align__(16) float          g_asrc[N];
__device__ __align__(16) float          g_adst[N];
__device__ __align__(16) float          g_Ssum[64];
__device__ __align__(16) float          g_part[GEMM_BLOCKS * 64];
__device__ unsigned                     g_fill[3];       // per-layer fill (ordered-int)
__device__ __align__(16) unsigned       g_selfmask[N / 32];  // cleared in last kernel
__device__ __align__(16) unsigned       g_bf[N * NW];    // cleared by k_build
__device__ __align__(16) unsigned       g_br[N * NW];
__device__ __align__(16) unsigned short g_nbr[N * LISTCAP];
__device__ __align__(16) int            g_cnt[N];

// ---------------- helpers ----------------
__device__ __forceinline__ float eluf(float x)  { return x > 0.f ? x : expf(x) - 1.f; }
__device__ __forceinline__ float lrelu(float x) { return fmaxf(x, 0.2f * x); }
__device__ __forceinline__ unsigned fmap(float f) {
    unsigned u = __float_as_uint(f);
    return (u & 0x80000000u) ? ~u : (u | 0x80000000u);
}
__device__ __forceinline__ float funmap(unsigned u) {
    return (u & 0x80000000u) ? __uint_as_float(u & 0x7fffffffu) : __uint_as_float(~u);
}
__device__ __forceinline__ unsigned h2u(__half2 h) {
    union { __half2 h; unsigned u; } c; c.h = h; return c.u;
}

// ---------------- kernels ----------------
// adjacency bits + self-edge bitmap; gid<N threads also do symbolic features.
// edge_index is int32 (JAX downcasts int64 without x64 mode).
__global__ void k_setbits_feat(const int* __restrict__ ei,
                               const float* __restrict__ x,
                               const float* __restrict__ symW,
                               const float* __restrict__ symb) {
    int gid = blockIdx.x * blockDim.x + threadIdx.x;
    if (gid == 0) { g_fill[0] = 0u; g_fill[1] = 0u; g_fill[2] = 0u; }
    int k0 = gid * 2;
    if (k0 < E) {
        int2 r2 = *(const int2*)(ei + k0);
        int2 c2 = *(const int2*)(ei + E + k0);
        if ((unsigned)r2.x < N && (unsigned)c2.x < N) {
            if (r2.x == c2.x) atomicOr(&g_selfmask[r2.x >> 5], 1u << (r2.x & 31));
            else {
                atomicOr(&g_bf[(r2.x << 8) + (c2.x >> 5)], 1u << (c2.x & 31));
                atomicOr(&g_br[(c2.x << 8) + (r2.x >> 5)], 1u << (r2.x & 31));
            }
        }
        if ((unsigned)r2.y < N && (unsigned)c2.y < N) {
            if (r2.y == c2.y) atomicOr(&g_selfmask[r2.y >> 5], 1u << (r2.y & 31));
            else {
                atomicOr(&g_bf[(r2.y << 8) + (c2.y >> 5)], 1u << (c2.y & 31));
                atomicOr(&g_br[(c2.y << 8) + (r2.y >> 5)], 1u << (r2.y & 31));
            }
        }
    }

    int i = gid;
    if (i >= N) return;
    const float* xr = x + i * 16;
    float am = xr[0], bod = xr[1], dox = xr[2], ph = xr[4], ni = xr[7];

    float p_ph  = ph  < 6.5f   ? (6.5f - ph) / 6.5f     : (ph  > 8.5f ? (ph  - 8.5f) / 8.5f : 0.f);
    float p_am  = am  < 0.001f ? (0.001f - am) / 0.001f : (am  > 0.5f ? (am  - 0.5f) / 0.5f : 0.f);
    float p_bod = bod < 0.001f ? (0.001f - bod) / 0.001f: (bod > 5.0f ? (bod - 5.0f) / 5.0f : 0.f);
    float p_do  = dox < 6.0f   ? (6.0f - dox) / 6.0f    : 0.f;
    float p_ni  = ni  < 0.001f ? (0.001f - ni) / 0.001f : (ni  > 10.f ? (ni  - 10.f) / 10.f : 0.f);

    float bact = (1.2f * am / 0.5f + 1.5f * bod / 5.0f - 0.8f * dox / 10.0f) * (1.f / 3.f);
    float chem = (1.5f * ph / 8.5f + ni / 10.0f) * 0.5f;
    float org  = (2.0f * bod / 5.0f - 1.5f * dox / 10.0f + 0.8f * am / 0.5f) * (1.f / 3.f);
    float agri = 2.0f * ni / 10.0f;
    float comp = 1.f / (1.f + (p_ph + p_am + p_bod + p_do + p_ni) + 1e-8f);

    float f[10] = { p_ph, p_am, p_bod, p_do, p_ni, bact, chem, org, agri, comp };
    float* hr = g_h + i * 64;
#pragma unroll
    for (int k = 0; k < 16; k++) hr[k] = xr[k];
    for (int j = 0; j < 32; j++) {
        float s = symb[j];
#pragma unroll
        for (int k = 0; k < 10; k++) s += f[k] * symW[j * 10 + k];
        hr[16 + j] = eluf(s);
    }
}

// one warp per row: bitmap -> canonical uint16 list; re-zero bitmap rows.
__global__ void k_build() {
    int warp = threadIdx.x >> 5;
    int lane = threadIdx.x & 31;
    int i = blockIdx.x * 8 + warp;

    unsigned* fw = g_bf + (i << 8);
    unsigned* rv = g_br + (i << 8);
    unsigned short* dst = g_nbr + i * LISTCAP;
    int total = 0;
    for (int it = 0; it < 8; it++) {
        int wi = it * 32 + lane;
        unsigned f = fw[wi];
        unsigned r = rv[wi];
        unsigned u = f | r;
        int cnt = __popc(u);
        int pre = cnt;
#pragma unroll
        for (int o = 1; o < 32; o <<= 1) {
            int t = __shfl_up_sync(0xffffffffu, pre, o);
            if (lane >= o) pre += t;
        }
        int wtot = __shfl_sync(0xffffffffu, pre, 31);
        int pos = total + pre - cnt;
        while (u) {
            int b = __ffs(u) - 1;
            u &= u - 1;
            unsigned F = (f >> b) & 1;
            unsigned R = (r >> b) & 1;
            if (pos < LISTCAP)
                dst[pos] = (unsigned short)((wi * 32 + b) | (F << 13) | (R << 14));
            pos++;
        }
        total += wtot;
        fw[wi] = 0u;
        rv[wi] = 0u;
    }
    if (total > LISTCAP) total = LISTCAP;
    if (lane == 0) g_cnt[i] = total;
}

// Fused: [mode>=1: inline combine of previous layer into g_h] ;
// ht = h @ W^T (fp32 + fp16 shadow) ; asrc/adst ; column partials.
// mode: 0 = plain load, 1 = combine (h = elu(r)), 2 = combine+residual.
__global__ void k_gemm_fused(const float* __restrict__ W,
                             const float* __restrict__ att, int K,
                             int mode, int fidx) {
    __shared__ __align__(16) float Ws[64][68];
    __shared__ float As[64][65];
    __shared__ float sAtt[128];
    __shared__ float spart[8][64];
    __shared__ float sZinv[64];
    __shared__ float sSs[64];
    __shared__ float sEnf, sEs;

    int tid = threadIdx.x;
    int rowBase = blockIdx.x * 64;

    for (int idx = tid; idx < 64 * K; idx += 256) {
        int c = idx / K, k = idx % K;
        Ws[k][c] = W[idx];
    }
    if (tid < 128) sAtt[tid] = att[tid];

    if (mode) {
        if (tid == 0) {
            float fill = funmap(g_fill[fidx]);
            sEnf = expf(-fill);
            sEs  = expf(SHIFT - fill);
        }
        if (tid < 64) sSs[tid] = g_Ssum[tid];
        __syncthreads();
        if (tid < 64) {
            float B = g_B[rowBase + tid];
            sZinv[tid] = 1.f / (1.f + 8191.f * sEnf + sEs * B);
        }
        __syncthreads();
        float enf = sEnf, es = sEs;
        for (int idx = tid; idx < 64 * K; idx += 256) {
            int r = idx / K, k = idx % K;
            int gi = (rowBase + r) * 64 + k;
            float A  = g_A[gi];
            float hi = g_ht[gi];
            float rr = (es * A + enf * sSs[k] + (1.f - enf) * hi) * sZinv[r];
            float e = eluf(rr);
            float hn = (mode == 2) ? g_h[gi] + e : e;
            g_h[gi] = hn;
            As[r][k] = hn;
        }
    } else {
        for (int idx = tid; idx < 64 * K; idx += 256) {
            int r = idx / K, k = idx % K;
            As[r][k] = g_h[(rowBase + r) * 64 + k];
        }
    }
    __syncthreads();

    int cg = tid & 7;
    int rg = tid >> 3;
    int r0 = rg * 2;
    int c0 = cg * 8;

    float acc0[8] = {}, acc1[8] = {};
    for (int k = 0; k < K; k++) {
        float a0 = As[r0][k];
        float a1 = As[r0 + 1][k];
        float4 w0 = *(const float4*)&Ws[k][c0];
        float4 w1 = *(const float4*)&Ws[k][c0 + 4];
        acc0[0] += a0 * w0.x; acc0[1] += a0 * w0.y; acc0[2] += a0 * w0.z; acc0[3] += a0 * w0.w;
        acc0[4] += a0 * w1.x; acc0[5] += a0 * w1.y; acc0[6] += a0 * w1.z; acc0[7] += a0 * w1.w;
        acc1[0] += a1 * w0.x; acc1[1] += a1 * w0.y; acc1[2] += a1 * w0.z; acc1[3] += a1 * w0.w;
        acc1[4] += a1 * w1.x; acc1[5] += a1 * w1.y; acc1[6] += a1 * w1.z; acc1[7] += a1 * w1.w;
    }

    int R0 = rowBase + r0;
    float4* hp0 = (float4*)(g_ht + R0 * 64 + c0);
    float4* hp1 = (float4*)(g_ht + (R0 + 1) * 64 + c0);
    hp0[0] = make_float4(acc0[0], acc0[1], acc0[2], acc0[3]);
    hp0[1] = make_float4(acc0[4], acc0[5], acc0[6], acc0[7]);
    hp1[0] = make_float4(acc1[0], acc1[1], acc1[2], acc1[3]);
    hp1[1] = make_float4(acc1[4], acc1[5], acc1[6], acc1[7]);

    *(uint4*)(g_hth + R0 * 64 + c0) = make_uint4(
        h2u(__floats2half2_rn(acc0[0], acc0[1])),
        h2u(__floats2half2_rn(acc0[2], acc0[3])),
        h2u(__floats2half2_rn(acc0[4], acc0[5])),
        h2u(__floats2half2_rn(acc0[6], acc0[7])));
    *(uint4*)(g_hth + (R0 + 1) * 64 + c0) = make_uint4(
        h2u(__floats2half2_rn(acc1[0], acc1[1])),
        h2u(__floats2half2_rn(acc1[2], acc1[3])),
        h2u(__floats2half2_rn(acc1[4], acc1[5])),
        h2u(__floats2half2_rn(acc1[6], acc1[7])));

    float s0 = 0.f, d0 = 0.f, s1 = 0.f, d1 = 0.f;
#pragma unroll
    for (int m = 0; m < 8; m++) {
        float aw = sAtt[c0 + m], dw = sAtt[64 + c0 + m];
        s0 += acc0[m] * aw;  d0 += acc0[m] * dw;
        s1 += acc1[m] * aw;  d1 += acc1[m] * dw;
    }
#pragma unroll
    for (int o = 1; o < 8; o <<= 1) {
        s0 += __shfl_xor_sync(0xffffffffu, s0, o);
        d0 += __shfl_xor_sync(0xffffffffu, d0, o);
        s1 += __shfl_xor_sync(0xffffffffu, s1, o);
        d1 += __shfl_xor_sync(0xffffffffu, d1, o);
    }
    if (cg == 0) {
        g_asrc[R0] = s0;  g_adst[R0] = d0;
        g_asrc[R0 + 1] = s1;  g_adst[R0 + 1] = d1;
    }

    int lane = tid & 31, warp = tid >> 5;
    float colv[8];
#pragma unroll
    for (int m = 0; m < 8; m++) {
        float v = acc0[m] + acc1[m];
        v += __shfl_xor_sync(0xffffffffu, v, 8);
        v += __shfl_xor_sync(0xffffffffu, v, 16);
        colv[m] = v;
    }
    if (lane < 8) {
#pragma unroll
        for (int m = 0; m < 8; m++) spart[warp][lane * 8 + m] = colv[m];
    }
    __syncthreads();
    if (tid < 64) {
        float s = 0.f;
#pragma unroll
        for (int w = 0; w < 8; w++) s += spart[w][tid];
        g_part[blockIdx.x * 64 + tid] = s;
    }
}

// one warp per row: unnormalized sparse aggregate A_i/B_i (shift S).
// Phase B: half-warp split — lanes 0-15 even entries, 16-31 odd entries,
// each lane owns 4 columns (LDG.64), merged via shfl_xor(16).
__global__ void k_agg2(int fidx) {
    __shared__ unsigned short list[8][LISTPAD];
    __shared__ float wbuf[8][LISTPAD];
    __shared__ float red[256];
    __shared__ float wfill[8];
    int tid = threadIdx.x;
    int warp = tid >> 5;
    int lane = tid & 31;
    int i = blockIdx.x * 8 + warp;

    if (blockIdx.x == 0) {
        int col = tid & 63, q = tid >> 6;
        float s = 0.f;
        for (int b = q; b < GEMM_BLOCKS; b += 4) s += g_part[b * 64 + col];
        red[tid] = s;
        __syncthreads();
        if (tid < 64) g_Ssum[tid] = red[tid] + red[64 + tid] + red[128 + tid] + red[192 + tid];
        // self-edge fill contributions (diag entries of e)
        unsigned mw = g_selfmask[tid];
        float sm = -3.0e38f;
        while (mw) {
            int b = __ffs(mw) - 1; mw &= mw - 1;
            int si = tid * 32 + b;
            sm = fmaxf(sm, lrelu(g_asrc[si] + g_adst[si]));
        }
        if (sm > -3.0e38f) atomicMax(&g_fill[fidx], fmap(sm));
    }

    int total = g_cnt[i];
    const unsigned* src = (const unsigned*)(g_nbr + i * LISTCAP);
    unsigned* dstw = (unsigned*)&list[warp][0];
    for (int t = lane; t * 2 < total; t += 32) dstw[t] = src[t];
    __syncwarp();

    // phase A: weights (fast exp, select-based lrelu); fwd-edge max for fill
    const float ENS = __expf(-SHIFT);
    float ai = g_asrc[i];
    float di = g_adst[i];
    float z = 0.f;
    float mv = -3.0e38f;
    for (int n = lane; n < total; n += 32) {
        unsigned ent = list[warp][n];
        int j = ent & 8191;
        float aj = g_asrc[j];
        float dj = g_adst[j];
        float e1 = (ent & (1u << 13)) ? lrelu(ai + dj) : 0.f;
        float e2 = (ent & (1u << 14)) ? lrelu(aj + di) : 0.f;
        mv = fmaxf(mv, (ent & (1u << 13)) ? e1 : -3.0e38f);
        float w = __expf(0.5f * (e1 + e2) - SHIFT) - ENS;
        wbuf[warp][n] = w;
        z += w;
    }
    if (lane == 0) {    // zero pad slot for odd totals (phase B reads index `total`)
        list[warp][total] = 0;
        wbuf[warp][total] = 0.f;
    }
#pragma unroll
    for (int o = 16; o; o >>= 1) {
        z  += __shfl_xor_sync(0xffffffffu, z, o);
        mv  = fmaxf(mv, __shfl_xor_sync(0xffffffffu, mv, o));
    }
    if (lane == 0) { g_B[i] = z; wfill[warp] = mv; }
    __syncthreads();
    if (tid == 0) {
        float bm = wfill[0];
#pragma unroll
        for (int w = 1; w < 8; w++) bm = fmaxf(bm, wfill[w]);
        if (bm > -3.0e38f) atomicMax(&g_fill[fidx], fmap(bm));
    }

    // phase B: half-warp split accumulation (4 cols per lane, LDG.64)
    int half = lane >> 4;           // 0: even entries, 1: odd entries
    int cidx = lane & 15;           // column group (4 half-cols)
    const __half* rowp = g_hth + cidx * 4;
    float a0 = 0.f, a1 = 0.f, a2 = 0.f, a3 = 0.f;
    int iters = (total + 1) >> 1;
    int n = half;
    int t = 0;
    for (; t + 1 < iters; t += 2, n += 4) {
        int   jA = list[warp][n] & 8191;
        float wA = wbuf[warp][n];
        int   jB = list[warp][n + 2] & 8191;
        float wB = wbuf[warp][n + 2];
        uint2 rA = *(const uint2*)(rowp + jA * 64);
        uint2 rB = *(const uint2*)(rowp + jB * 64);
        float2 pA = __half22float2(*(__half2*)&rA.x);
        float2 qA = __half22float2(*(__half2*)&rA.y);
        float2 pB = __half22float2(*(__half2*)&rB.x);
        float2 qB = __half22float2(*(__half2*)&rB.y);
        a0 += wA * pA.x + wB * pB.x;
        a1 += wA * pA.y + wB * pB.y;
        a2 += wA * qA.x + wB * qB.x;
        a3 += wA * qA.y + wB * qB.y;
    }
    if (t < iters) {
        int   jA = list[warp][n] & 8191;
        float wA = wbuf[warp][n];
        uint2 rA = *(const uint2*)(rowp + jA * 64);
        float2 pA = __half22float2(*(__half2*)&rA.x);
        float2 qA = __half22float2(*(__half2*)&rA.y);
        a0 += wA * pA.x;
        a1 += wA * pA.y;
        a2 += wA * qA.x;
        a3 += wA * qA.y;
    }
    a0 += __shfl_xor_sync(0xffffffffu, a0, 16);
    a1 += __shfl_xor_sync(0xffffffffu, a1, 16);
    a2 += __shfl_xor_sync(0xffffffffu, a2, 16);
    a3 += __shfl_xor_sync(0xffffffffu, a3, 16);
    if (lane < 16)
        *(float4*)(g_A + i * 64 + cidx * 4) = make_float4(a0, a1, a2, a3);
}

// final: combine layer-2 aggregate + residual + both head MLPs + outputs.
// Also clears g_selfmask for the next replay (no reader of it here).
__global__ void k_combine_heads(const float* __restrict__ rW1, const float* __restrict__ rb1,
                                const float* __restrict__ rW2, const float* __restrict__ rb2,
                                const float* __restrict__ cW1, const float* __restrict__ cb1,
                                const float* __restrict__ cW2, const float* __restrict__ cb2,
                                float* __restrict__ out) {
    __shared__ float sRW1[32][65];
    __shared__ float sCW1[32][65];
    __shared__ float sRW2[32];
    __shared__ float sCW2[128];
    __shared__ float sRb1[32];
    __shared__ float sCb1[32];
    __shared__ float srow[8][64];
    __shared__ float sEnf, sEs;

    int tid = threadIdx.x;
    int warp = tid >> 5;
    int lane = tid & 31;
    int i = blockIdx.x * 8 + warp;
    int c0 = lane * 2;

    if (blockIdx.x == 0) g_selfmask[tid] = 0u;   // blockDim==256==N/32

    for (int idx = tid; idx < 2048; idx += 256) {
        sRW1[idx >> 6][idx & 63] = rW1[idx];
        sCW1[idx >> 6][idx & 63] = cW1[idx];
    }
    if (tid < 32) { sRW2[tid] = rW2[tid]; sRb1[tid] = rb1[tid]; sCb1[tid] = cb1[tid]; }
    if (tid < 128) sCW2[tid] = cW2[tid];
    if (tid == 0) {
        float fill = funmap(g_fill[2]);
        sEnf = expf(-fill);
        sEs  = expf(SHIFT - fill);
    }
    __syncthreads();

    float enf = sEnf, es = sEs;
    float Zinv;
    if (lane == 0) Zinv = 1.f / (1.f + 8191.f * enf + es * g_B[i]);
    Zinv = __shfl_sync(0xffffffffu, Zinv, 0);

    float A0 = g_A[i * 64 + c0], A1 = g_A[i * 64 + c0 + 1];
    float hi0 = g_ht[i * 64 + c0], hi1 = g_ht[i * 64 + c0 + 1];
    float r0 = (es * A0 + enf * g_Ssum[c0]     + (1.f - enf) * hi0) * Zinv;
    float r1 = (es * A1 + enf * g_Ssum[c0 + 1] + (1.f - enf) * hi1) * Zinv;
    float h0 = g_h[i * 64 + c0]     + eluf(r0);
    float h1 = g_h[i * 64 + c0 + 1] + eluf(r1);

    srow[warp][c0]     = h0;
    srow[warp][c0 + 1] = h1;
    __syncwarp();

    float t1 = sRb1[lane];
    float t2 = sCb1[lane];
#pragma unroll
    for (int k = 0; k < 64; k++) {
        float hv = srow[warp][k];
        t1 += hv * sRW1[lane][k];
        t2 += hv * sCW1[lane][k];
    }
    t1 = eluf(t1);
    t2 = eluf(t2);

    float p = t1 * sRW2[lane];
#pragma unroll
    for (int o = 16; o; o >>= 1) p += __shfl_xor_sync(0xffffffffu, p, o);
    if (lane == 0) out[i] = p + rb2[0];

#pragma unroll
    for (int k = 0; k < 4; k++) {
        float q = t2 * sCW2[k * 32 + lane];
#pragma unroll
        for (int o = 16; o; o >>= 1) q += __shfl_xor_sync(0xffffffffu, q, o);
        if (lane == 0) out[N + i * 4 + k] = q + cb2[k];
    }

    ((float2*)(out + N + 4 * N))[i * 32 + lane] = make_float2(h0, h1);
}

// ---------------- launch ----------------
extern "C" void kernel_launch(void* const* d_in, const int* in_sizes, int n_in,
                              void* d_out, int out_size) {
    const float* x    = (const float*)d_in[0];
    const int*   ei   = (const int*)d_in[1];   // int32 (JAX downcast)
    const float* symW = (const float*)d_in[3];
    const float* symb = (const float*)d_in[4];
    const float* W0   = (const float*)d_in[5];
    const float* att0 = (const float*)d_in[6];
    const float* W1   = (const float*)d_in[7];
    const float* att1 = (const float*)d_in[8];
    const float* W2   = (const float*)d_in[9];
    const float* att2 = (const float*)d_in[10];
    const float* rW1  = (const float*)d_in[11];
    const float* rb1  = (const float*)d_in[12];
    const float* rW2  = (const float*)d_in[13];
    const float* rb2  = (const float*)d_in[14];
    const float* cW1  = (const float*)d_in[15];
    const float* cb1  = (const float*)d_in[16];
    const float* cW2  = (const float*)d_in[17];
    const float* cb2  = (const float*)d_in[18];
    float* out = (float*)d_out;

    k_setbits_feat<<<SB_BLOCKS, 256>>>(ei, x, symW, symb);
    k_build<<<1024, 256>>>();

    k_gemm_fused<<<GEMM_BLOCKS, 256>>>(W0, att0, 48, 0, 0);
    k_agg2<<<1024, 256>>>(0);
    k_gemm_fused<<<GEMM_BLOCKS, 256>>>(W1, att1, 64, 1, 0);   // inline combine L0
    k_agg2<<<1024, 256>>>(1);
    k_gemm_fused<<<GEMM_BLOCKS, 256>>>(W2, att2, 64, 2, 1);   // inline combine L1 (+resid)
    k_agg2<<<1024, 256>>>(2);
    k_combine_heads<<<1024, 256>>>(rW1, rb1, rW2, rb2, cW1, cb1, cW2, cb2, out);
}